// round 9
// baseline (speedup 1.0000x reference)
#include <cuda_runtime.h>
#include <cuda_bf16.h>
#include <cstdint>

#define B_   4
#define V_   778
#define F_   1538
#define RW   256
#define NPIX (RW * RW)
#define FARV 10.0f
#define TILE 16
#define TCS  208           // per-subtile list capacity (>= SLICE)
#define S_   8             // triangle slices per batch
#define SLICE ((F_ + S_ - 1) / S_)   // 193
#define DXS  0.03125f      // subtile center offset from block center (4px in NDC)
#define HXS  0.02734375f   // subtile half-extent (7px span / 2 in NDC = 7/256)

// ---------------- scratch (static device globals; no allocation) -------------
__device__ float4   g_e0  [B_ * F_];   // U0,V0,W0,|U0|+|V0|
__device__ float4   g_e1  [B_ * F_];
__device__ float4   g_e2  [B_ * F_];
__device__ float4   g_gi  [B_ * F_];   // Gx,Gy,Gc,-
__device__ float4   g_bbox[B_ * F_];   // xmin,xmax,ymin,ymax
__device__ unsigned g_inv [B_ * NPIX];
__device__ unsigned g_mx  [B_];
__device__ unsigned g_mn  [B_];
__device__ unsigned g_cnt;

// ---------------- projection helper ------------------------------------------
__device__ __forceinline__ float3 proj_vert(const float* __restrict__ verts,
                                            const float* __restrict__ Rb,
                                            const float* __restrict__ tb,
                                            const float* __restrict__ Kb,
                                            const float* __restrict__ db,
                                            int vglob) {
    const float* p = verts + vglob * 3;
    float px = p[0], py = p[1], pz = p[2];
    float x = Rb[0]*px + Rb[1]*py + Rb[2]*pz + tb[0];
    float y = Rb[3]*px + Rb[4]*py + Rb[5]*pz + tb[1];
    float z = Rb[6]*px + Rb[7]*py + Rb[8]*pz + tb[2];

    float zi = z + 1e-9f;
    float x_ = x / zi, y_ = y / zi;
    float k1 = db[0], k2 = db[1], p1 = db[2], p2 = db[3], k3 = db[4];
    float r2 = x_*x_ + y_*y_;
    float radial = 1.0f + k1*r2 + k2*r2*r2 + k3*r2*r2*r2;
    float x2 = x_*radial + 2.0f*p1*x_*y_ + p2*(r2 + 2.0f*x_*x_);
    float y2 = y_*radial + p1*(r2 + 2.0f*y_*y_) + 2.0f*p2*x_*y_;
    float u  = Kb[0]*x2 + Kb[1]*y2 + Kb[2];
    float vv = Kb[3]*x2 + Kb[4]*y2 + Kb[5];
    vv = 256.0f - vv;
    u  = 2.0f * (u  - 128.0f) / 256.0f;
    vv = 2.0f * (vv - 128.0f) / 256.0f;
    return make_float3(u, vv, z);
}

// ---------------- K1: fused setup + scratch clear ----------------------------
__global__ void __launch_bounds__(256) k_prep(const float* __restrict__ verts,
                                              const int*   __restrict__ faces,
                                              const float* __restrict__ intr,
                                              const float* __restrict__ R,
                                              const float* __restrict__ t,
                                              const float* __restrict__ dist) {
    int gid = blockIdx.x * 256 + threadIdx.x;

    if (gid < B_ * F_) {
        int b  = gid / F_;
        const float* Rb = R    + b * 9;
        const float* tb = t    + b * 3;
        const float* Kb = intr + b * 9;
        const float* db = dist + b * 5;

        int base = gid * 3;
        int i0 = faces[base + 0], i1 = faces[base + 1], i2 = faces[base + 2];

        float3 A  = proj_vert(verts, Rb, tb, Kb, db, b * V_ + i0);
        float3 Bv = proj_vert(verts, Rb, tb, Kb, db, b * V_ + i1);
        float3 Cv = proj_vert(verts, Rb, tb, Kb, db, b * V_ + i2);
        float ax = A.x,  ay = A.y,  az = A.z;
        float bx = Bv.x, by = Bv.y, bz = Bv.z;
        float cx = Cv.x, cy = Cv.y, cz = Cv.z;

        float den = (bx - ax) * (cy - ay) - (by - ay) * (cx - ax);
        bool ok = (fabsf(den) > 1e-8f) && (az > 1e-8f) && (bz > 1e-8f) && (cz > 1e-8f);

        float4 e0, e1, e2, gi, bb;
        if (!ok) {
            e0 = make_float4(0.f, 0.f, -1e30f, 0.f);
            e1 = make_float4(0.f, 0.f, 0.f, 0.f);
            e2 = make_float4(0.f, 0.f, 0.f, 0.f);
            gi = make_float4(0.f, 0.f, 0.f, 0.f);
            bb = make_float4(2e30f, -2e30f, 2e30f, -2e30f);
        } else {
            float id = 1.0f / den;
            float U0 = (by - cy) * id, V0 = (cx - bx) * id;
            float W0 = -(U0 * cx + V0 * cy);
            float U1 = (cy - ay) * id, V1 = (ax - cx) * id;
            float W1 = -(U1 * cx + V1 * cy);
            float U2 = -(U0 + U1), V2 = -(V0 + V1), W2 = 1.0f - W0 - W1;
            float ra = 1.0f / az, rb = 1.0f / bz, rc = 1.0f / cz;
            float dA = ra - rc, dB = rb - rc;
            float Gx = U0 * dA + U1 * dB;
            float Gy = V0 * dA + V1 * dB;
            float Gc = rc + W0 * dA + W1 * dB;
            e0 = make_float4(U0, V0, W0, fabsf(U0) + fabsf(V0));
            e1 = make_float4(U1, V1, W1, fabsf(U1) + fabsf(V1));
            e2 = make_float4(U2, V2, W2, fabsf(U2) + fabsf(V2));
            gi = make_float4(Gx, Gy, Gc, 0.f);
            bb = make_float4(fminf(ax, fminf(bx, cx)), fmaxf(ax, fmaxf(bx, cx)),
                             fminf(ay, fminf(by, cy)), fmaxf(ay, fmaxf(by, cy)));
        }
        g_e0[gid] = e0; g_e1[gid] = e1; g_e2[gid] = e2;
        g_gi[gid] = gi; g_bbox[gid] = bb;
    }

    reinterpret_cast<uint4*>(g_inv)[gid] = make_uint4(0u, 0u, 0u, 0u);
    if (gid < B_) { g_mx[gid] = 0u; g_mn[gid] = __float_as_uint(FARV); }
    if (gid == 0) g_cnt = 0u;
}

// ---------------- K2: subtile-classified rasterizer --------------------------
// block = 16x16 px; classification per 8x8 subtile; 8 triangle slices
__global__ void __launch_bounds__(256) k_raster() {
    __shared__ float4 spA[4][TCS], spB[4][TCS];
    __shared__ float  spC[4][TCS];
    __shared__ float4 sfl[4][TCS];
    __shared__ int    nP[4], nF[4];

    int bz = blockIdx.z;
    int b  = bz & (B_ - 1);
    int sl = bz >> 2;
    int t0 = sl * SLICE;
    int t1 = min(F_, t0 + SLICE);

    int tid  = threadIdx.x;
    int sub  = tid >> 6;             // subtile 0..3
    int lane = tid & 63;
    int tx   = blockIdx.x * TILE;
    int ty   = blockIdx.y * TILE;
    int ix   = tx + (sub & 1) * 8 + (lane & 7);
    int iy   = ty + (sub >> 1) * 8 + (lane >> 3);

    float x = 2.0f * (ix + 0.5f) / 256.0f - 1.0f;
    float y = 2.0f * (iy + 0.5f) / 256.0f - 1.0f;

    // block bounds / center
    float xlo = 2.0f * (tx +  0.5f) / 256.0f - 1.0f;
    float xhi = 2.0f * (tx + 15.5f) / 256.0f - 1.0f;
    float ylo = 2.0f * (ty +  0.5f) / 256.0f - 1.0f;
    float yhi = 2.0f * (ty + 15.5f) / 256.0f - 1.0f;
    float xc  = 0.5f * (xlo + xhi);
    float yc  = 0.5f * (ylo + yhi);

    const float4* e0p  = g_e0   + b * F_;
    const float4* e1p  = g_e1   + b * F_;
    const float4* e2p  = g_e2   + b * F_;
    const float4* gip  = g_gi   + b * F_;
    const float4* bbox = g_bbox + b * F_;

    if (tid < 4) { nP[tid] = 0; nF[tid] = 0; }
    __syncthreads();

    int tI = t0 + tid;
    if (tI < t1) {
        float4 bb = bbox[tI];
        if (bb.x <= xhi && bb.y >= xlo && bb.z <= yhi && bb.w >= ylo) {
            float4 r0 = e0p[tI];
            float4 r1 = e1p[tI];
            float4 r2 = e2p[tI];
            float cv0 = fmaf(r0.x, xc, fmaf(r0.y, yc, r0.z));
            float cv1 = fmaf(r1.x, xc, fmaf(r1.y, yc, r1.z));
            float cv2 = fmaf(r2.x, xc, fmaf(r2.y, yc, r2.z));
            float du0 = r0.x * DXS, dv0 = r0.y * DXS, E0 = r0.w * HXS;
            float du1 = r1.x * DXS, dv1 = r1.y * DXS, E1 = r1.w * HXS;
            float du2 = r2.x * DXS, dv2 = r2.y * DXS, E2 = r2.w * HXS;
            float me0 = fmaf(E0, 2e-6f, 1e-6f);
            float me1 = fmaf(E1, 2e-6f, 1e-6f);
            float me2 = fmaf(E2, 2e-6f, 1e-6f);
            float4 gi = gip[tI];

            #pragma unroll
            for (int s = 0; s < 4; s++) {
                // subtile bbox bounds
                float sxlo = (s & 1) ? xc : xlo;
                float sxhi = (s & 1) ? xhi : xc;
                float sylo = (s & 2) ? yc : ylo;
                float syhi = (s & 2) ? yhi : yc;
                if (bb.x > sxhi || bb.y < sxlo || bb.z > syhi || bb.w < sylo) continue;

                float c0 = cv0 + ((s & 1) ? du0 : -du0) + ((s & 2) ? dv0 : -dv0);
                float c1 = cv1 + ((s & 1) ? du1 : -du1) + ((s & 2) ? dv1 : -dv1);
                float c2 = cv2 + ((s & 1) ? du2 : -du2) + ((s & 2) ? dv2 : -dv2);

                bool rej = (c0 + E0 < -me0) || (c1 + E1 < -me1) || (c2 + E2 < -me2);
                if (rej) continue;
                bool full = (c0 - E0 > me0) && (c1 - E1 > me1) && (c2 - E2 > me2);
                if (full) {
                    int k = atomicAdd(&nF[s], 1);
                    sfl[s][k] = gi;
                } else {
                    int k = atomicAdd(&nP[s], 1);
                    spA[s][k] = make_float4(r0.x, r0.y, r0.z, r1.x);
                    spB[s][k] = make_float4(r1.y, r1.z, gi.x, gi.y);
                    spC[s][k] = gi.z;
                }
            }
        }
    }
    __syncthreads();
    int np = nP[sub], nf = nF[sub];

    float m = 0.f;

    // partial: per-pixel test (R4/R6-proven form)
    for (int j = 0; j < np; j++) {
        float4 a = spA[sub][j];
        float4 c = spB[sub][j];
        float gc = spC[sub][j];
        float w0 = fmaf(a.x, x, fmaf(a.y, y, a.z));
        float w1 = fmaf(a.w, x, fmaf(c.x, y, c.y));
        float w2 = (1.0f - w0) - w1;
        float iv = fmaf(c.z, x, fmaf(c.w, y, gc));
        unsigned s = __float_as_uint(w0) | __float_as_uint(w1) | __float_as_uint(w2);
        m = fmaxf(m, __uint_as_float(__float_as_uint(iv) | (s & 0x80000000u)));
    }

    // full-accept
    #pragma unroll 2
    for (int j = 0; j < nf; j++) {
        float4 f = sfl[sub][j];
        m = fmaxf(m, fmaf(f.x, x, fmaf(f.y, y, f.z)));
    }

    if (m > 0.f) atomicMax(g_inv + b * NPIX + iy * RW + ix, __float_as_uint(m));
}

// ---------------- K3: fused zpass + normalize (resident-grid barrier) --------
// 256 blocks (all resident on 148 SMs) — spin barrier is deadlock-free
__global__ void __launch_bounds__(256) k_final(float* __restrict__ dep,
                                               float* __restrict__ mask) {
    __shared__ float smx[256], smn[256];
    __shared__ float sMx, sMn;
    int idx4 = blockIdx.x * 256 + threadIdx.x;   // 0..65535 (uint4 index)
    int b    = idx4 >> 14;                       // constant per block
    int tid  = threadIdx.x;

    uint4 mi = reinterpret_cast<const uint4*>(g_inv)[idx4];
    float z0 = mi.x ? fminf(FARV, 1.0f / __uint_as_float(mi.x)) : FARV;
    float z1 = mi.y ? fminf(FARV, 1.0f / __uint_as_float(mi.y)) : FARV;
    float z2 = mi.z ? fminf(FARV, 1.0f / __uint_as_float(mi.z)) : FARV;
    float z3 = mi.w ? fminf(FARV, 1.0f / __uint_as_float(mi.w)) : FARV;

    reinterpret_cast<float4*>(mask)[idx4] = make_float4(mi.x ? 1.f : 0.f,
                                                        mi.y ? 1.f : 0.f,
                                                        mi.z ? 1.f : 0.f,
                                                        mi.w ? 1.f : 0.f);

    float fx0 = (mi.x && z0 < FARV) ? z0 : 0.f;
    float fx1 = (mi.y && z1 < FARV) ? z1 : 0.f;
    float fx2 = (mi.z && z2 < FARV) ? z2 : 0.f;
    float fx3 = (mi.w && z3 < FARV) ? z3 : 0.f;

    smx[tid] = fmaxf(fmaxf(fx0, fx1), fmaxf(fx2, fx3));
    smn[tid] = fminf(fminf(z0, z1), fminf(z2, z3));
    __syncthreads();
    for (int s = 128; s > 0; s >>= 1) {
        if (tid < s) {
            smx[tid] = fmaxf(smx[tid], smx[tid + s]);
            smn[tid] = fminf(smn[tid], smn[tid + s]);
        }
        __syncthreads();
    }
    if (tid == 0) {
        atomicMax(&g_mx[b], __float_as_uint(smx[0]));
        atomicMin(&g_mn[b], __float_as_uint(smn[0]));
        __threadfence();
        atomicAdd(&g_cnt, 1u);
        while (atomicAdd(&g_cnt, 0u) < (unsigned)gridDim.x) { }
        sMx = __uint_as_float(atomicAdd(&g_mx[b], 0u));
        sMn = __uint_as_float(atomicAdd(&g_mn[b], 0u));
    }
    __syncthreads();

    float mx = sMx;
    float rd = 1.0f / (mx - sMn + 1e-4f);
    float4 o;
    o.x = fminf(fmaxf((mx - z0) * rd, 0.0f), 1.0f);
    o.y = fminf(fmaxf((mx - z1) * rd, 0.0f), 1.0f);
    o.z = fminf(fmaxf((mx - z2) * rd, 0.0f), 1.0f);
    o.w = fminf(fmaxf((mx - z3) * rd, 0.0f), 1.0f);
    reinterpret_cast<float4*>(dep)[idx4] = o;
}

// ---------------- launch ------------------------------------------------------
extern "C" void kernel_launch(void* const* d_in, const int* in_sizes, int n_in,
                              void* d_out, int out_size) {
    const float* vertices = (const float*)d_in[0];
    const int*   faces    = (const int*)  d_in[1];
    const float* intr     = (const float*)d_in[2];
    const float* R        = (const float*)d_in[3];
    const float* t        = (const float*)d_in[4];
    const float* dist     = (const float*)d_in[5];

    float* out  = (float*)d_out;
    float* dep  = out;
    float* mask = out + B_ * NPIX;

    k_prep<<<256, 256>>>(vertices, faces, intr, R, t, dist);
    dim3 grid(RW / TILE, RW / TILE, B_ * S_);
    k_raster<<<grid, 256>>>();
    k_final<<<256, 256>>>(dep, mask);
}

// round 10
// speedup vs baseline: 1.8037x; 1.8037x over previous
#include <cuda_runtime.h>
#include <cuda_bf16.h>
#include <cstdint>

#define B_   4
#define V_   778
#define F_   1538
#define RW   256
#define NPIX (RW * RW)
#define FARV 10.0f
#define TILE 16
#define TC   256
#define HX   0.05859375f   // 16x16 tile half-extent in NDC (15px span/2 * 2/256)

// ---------------- scratch (static device globals; no allocation) -------------
__device__ float    g_uvz [B_ * V_ * 3];
__device__ float4   g_e0  [B_ * F_];   // U0,V0,W0,|U0|+|V0|
__device__ float4   g_e1  [B_ * F_];
__device__ float4   g_e2  [B_ * F_];
__device__ float4   g_gi  [B_ * F_];   // Gx,Gy,Gc,-
__device__ float4   g_bbox[B_ * F_];
__device__ unsigned g_mx  [B_];
__device__ unsigned g_mn  [B_];

// ---------------- K1: project vertices + clear reductions --------------------
__global__ void __launch_bounds__(256) k_project(const float* __restrict__ verts,
                                                 const float* __restrict__ intr,
                                                 const float* __restrict__ R,
                                                 const float* __restrict__ t,
                                                 const float* __restrict__ dist) {
    int idx = blockIdx.x * 256 + threadIdx.x;
    if (idx < B_) { g_mx[idx] = 0u; g_mn[idx] = __float_as_uint(FARV); }
    if (idx >= B_ * V_) return;
    int b = idx / V_;
    const float* p  = verts + idx * 3;
    const float* Rb = R    + b * 9;
    const float* tb = t    + b * 3;
    const float* Kb = intr + b * 9;
    const float* db = dist + b * 5;

    float px = p[0], py = p[1], pz = p[2];
    float x = Rb[0]*px + Rb[1]*py + Rb[2]*pz + tb[0];
    float y = Rb[3]*px + Rb[4]*py + Rb[5]*pz + tb[1];
    float z = Rb[6]*px + Rb[7]*py + Rb[8]*pz + tb[2];

    float zi = z + 1e-9f;
    float x_ = x / zi, y_ = y / zi;
    float k1 = db[0], k2 = db[1], p1 = db[2], p2 = db[3], k3 = db[4];
    float r2 = x_*x_ + y_*y_;
    float radial = 1.0f + k1*r2 + k2*r2*r2 + k3*r2*r2*r2;
    float x2 = x_*radial + 2.0f*p1*x_*y_ + p2*(r2 + 2.0f*x_*x_);
    float y2 = y_*radial + p1*(r2 + 2.0f*y_*y_) + 2.0f*p2*x_*y_;
    float u  = Kb[0]*x2 + Kb[1]*y2 + Kb[2];
    float vv = Kb[3]*x2 + Kb[4]*y2 + Kb[5];
    vv = 256.0f - vv;
    u  = 2.0f * (u  - 128.0f) / 256.0f;
    vv = 2.0f * (vv - 128.0f) / 256.0f;

    g_uvz[idx*3 + 0] = u;
    g_uvz[idx*3 + 1] = vv;
    g_uvz[idx*3 + 2] = z;
}

// ---------------- K2: triangle setup -----------------------------------------
__global__ void __launch_bounds__(256) k_setup(const int* __restrict__ faces) {
    int gid = blockIdx.x * 256 + threadIdx.x;
    if (gid >= B_ * F_) return;
    int b = gid / F_;

    int base = gid * 3;
    int i0 = faces[base + 0], i1 = faces[base + 1], i2 = faces[base + 2];

    const float* va = g_uvz + (b * V_ + i0) * 3;
    const float* vb = g_uvz + (b * V_ + i1) * 3;
    const float* vc = g_uvz + (b * V_ + i2) * 3;
    float ax = va[0], ay = va[1], az = va[2];
    float bx = vb[0], by = vb[1], bz = vb[2];
    float cx = vc[0], cy = vc[1], cz = vc[2];

    float den = (bx - ax) * (cy - ay) - (by - ay) * (cx - ax);
    bool ok = (fabsf(den) > 1e-8f) && (az > 1e-8f) && (bz > 1e-8f) && (cz > 1e-8f);

    float4 e0, e1, e2, gi, bb;
    if (!ok) {
        e0 = make_float4(0.f, 0.f, -1e30f, 0.f);
        e1 = make_float4(0.f, 0.f, 0.f, 0.f);
        e2 = make_float4(0.f, 0.f, 0.f, 0.f);
        gi = make_float4(0.f, 0.f, 0.f, 0.f);
        bb = make_float4(2e30f, -2e30f, 2e30f, -2e30f);
    } else {
        float id = 1.0f / den;
        float U0 = (by - cy) * id, V0 = (cx - bx) * id;
        float W0 = -(U0 * cx + V0 * cy);
        float U1 = (cy - ay) * id, V1 = (ax - cx) * id;
        float W1 = -(U1 * cx + V1 * cy);
        float U2 = -(U0 + U1), V2 = -(V0 + V1), W2 = 1.0f - W0 - W1;
        float ra = 1.0f / az, rb = 1.0f / bz, rc = 1.0f / cz;
        float dA = ra - rc, dB = rb - rc;
        float Gx = U0 * dA + U1 * dB;
        float Gy = V0 * dA + V1 * dB;
        float Gc = rc + W0 * dA + W1 * dB;
        e0 = make_float4(U0, V0, W0, fabsf(U0) + fabsf(V0));
        e1 = make_float4(U1, V1, W1, fabsf(U1) + fabsf(V1));
        e2 = make_float4(U2, V2, W2, fabsf(U2) + fabsf(V2));
        gi = make_float4(Gx, Gy, Gc, 0.f);
        bb = make_float4(fminf(ax, fminf(bx, cx)), fmaxf(ax, fmaxf(bx, cx)),
                         fminf(ay, fminf(by, cy)), fmaxf(ay, fmaxf(by, cy)));
    }
    g_e0[gid] = e0; g_e1[gid] = e1; g_e2[gid] = e2;
    g_gi[gid] = gi; g_bbox[gid] = bb;
}

// ---------------- K3: rasterizer with hierarchical-Z pruning -----------------
// grid (16,16,B_): one block owns a 16x16 tile over ALL F_ triangles.
// Plain stores (single writer per pixel); fused z-pass + block min/max.
__global__ void __launch_bounds__(256) k_raster(float* __restrict__ dep,
                                                float* __restrict__ mask) {
    __shared__ float4   spA[TC], spB[TC];
    __shared__ float    spC[TC];
    __shared__ float4   sfl[TC];
    __shared__ int      nP, nF;
    __shared__ unsigned sL;            // running lower bound of tile depth-max (inv)
    __shared__ float    smx[256], smn[256];

    int b   = blockIdx.z;
    int tid = threadIdx.x;
    int tx  = blockIdx.x * TILE;
    int ty  = blockIdx.y * TILE;
    int ix  = tx + (tid & 15);
    int iy  = ty + (tid >> 4);

    float x = 2.0f * (ix + 0.5f) / 256.0f - 1.0f;
    float y = 2.0f * (iy + 0.5f) / 256.0f - 1.0f;

    float xlo = 2.0f * (tx +  0.5f) / 256.0f - 1.0f;
    float xhi = 2.0f * (tx + 15.5f) / 256.0f - 1.0f;
    float ylo = 2.0f * (ty +  0.5f) / 256.0f - 1.0f;
    float yhi = 2.0f * (ty + 15.5f) / 256.0f - 1.0f;
    float xc  = 0.5f * (xlo + xhi);
    float yc  = 0.5f * (ylo + yhi);

    const float4* e0p  = g_e0   + b * F_;
    const float4* e1p  = g_e1   + b * F_;
    const float4* e2p  = g_e2   + b * F_;
    const float4* gip  = g_gi   + b * F_;
    const float4* bbox = g_bbox + b * F_;

    if (tid == 0) sL = 0u;
    float m = 0.f;

    for (int c0 = 0; c0 < F_; c0 += TC) {
        // ---- reset list counters (sL persists across chunks) ----
        __syncthreads();
        if (tid == 0) { nP = 0; nF = 0; }
        __syncthreads();

        // ---- phase A: classify own triangle, update occlusion bound ----
        bool   isF = false, isP = false;
        float4 r0, r1, r2, gi;
        float  ivc = 0.f, Ei = 0.f;
        int tI = c0 + tid;
        if (tI < F_) {
            float4 bb = bbox[tI];
            if (bb.x <= xhi && bb.y >= xlo && bb.z <= yhi && bb.w >= ylo) {
                r0 = e0p[tI]; r1 = e1p[tI]; r2 = e2p[tI];
                float cv0 = fmaf(r0.x, xc, fmaf(r0.y, yc, r0.z));
                float cv1 = fmaf(r1.x, xc, fmaf(r1.y, yc, r1.z));
                float cv2 = fmaf(r2.x, xc, fmaf(r2.y, yc, r2.z));
                float E0 = r0.w * HX, E1 = r1.w * HX, E2 = r2.w * HX;
                float me0 = fmaf(E0, 2e-6f, 1e-6f);
                float me1 = fmaf(E1, 2e-6f, 1e-6f);
                float me2 = fmaf(E2, 2e-6f, 1e-6f);

                bool rej = (cv0 + E0 < -me0) || (cv1 + E1 < -me1) || (cv2 + E2 < -me2);
                if (!rej) {
                    gi  = gip[tI];
                    ivc = fmaf(gi.x, xc, fmaf(gi.y, yc, gi.z));
                    Ei  = (fabsf(gi.x) + fabsf(gi.y)) * HX;
                    bool full = (cv0 - E0 > me0) && (cv1 - E1 > me1) && (cv2 - E2 > me2);
                    if (full) {
                        isF = true;
                        atomicMax(&sL, __float_as_uint(fmaxf(ivc - Ei, 0.f)));
                    } else {
                        isP = true;
                    }
                }
            }
        }
        __syncthreads();

        // ---- phase B: append survivors of the depth prune ----
        float L = __uint_as_float(sL) - 2e-5f;
        if (isF && (ivc + Ei >= L)) {
            int k = atomicAdd(&nF, 1);
            sfl[k] = gi;
        } else if (isP && (ivc + Ei >= L)) {
            int k = atomicAdd(&nP, 1);
            spA[k] = make_float4(r0.x, r0.y, r0.z, r1.x);
            spB[k] = make_float4(r1.y, r1.z, gi.x, gi.y);
            spC[k] = gi.z;
        }
        __syncthreads();
        int np = nP, nf = nF;

        // ---- partial loop (R4/R6-proven form) ----
        for (int j = 0; j < np; j++) {
            float4 a = spA[j];
            float4 c = spB[j];
            float gc = spC[j];
            float w0 = fmaf(a.x, x, fmaf(a.y, y, a.z));
            float w1 = fmaf(a.w, x, fmaf(c.x, y, c.y));
            float w2 = (1.0f - w0) - w1;
            float iv = fmaf(c.z, x, fmaf(c.w, y, gc));
            unsigned s = __float_as_uint(w0) | __float_as_uint(w1) | __float_as_uint(w2);
            m = fmaxf(m, __uint_as_float(__float_as_uint(iv) | (s & 0x80000000u)));
        }

        // ---- full-accept loop ----
        #pragma unroll 2
        for (int j = 0; j < nf; j++) {
            float4 f = sfl[j];
            m = fmaxf(m, fmaf(f.x, x, fmaf(f.y, y, f.z)));
        }
    }

    // ---- fused z-pass: single writer per pixel ----
    bool  cov = m > 0.f;
    float z   = cov ? fminf(FARV, 1.0f / m) : FARV;
    int   pix = b * NPIX + iy * RW + ix;
    dep [pix] = z;                       // raw z; normalized by k_final
    mask[pix] = cov ? 1.0f : 0.0f;

    smx[tid] = (cov && z < FARV) ? z : 0.0f;
    smn[tid] = z;
    __syncthreads();
    for (int s = 128; s > 0; s >>= 1) {
        if (tid < s) {
            smx[tid] = fmaxf(smx[tid], smx[tid + s]);
            smn[tid] = fminf(smn[tid], smn[tid + s]);
        }
        __syncthreads();
    }
    if (tid == 0) {
        atomicMax(&g_mx[b], __float_as_uint(smx[0]));
        atomicMin(&g_mn[b], __float_as_uint(smn[0]));
    }
}

// ---------------- K4: depth normalization (float4, in place) -----------------
__global__ void __launch_bounds__(256) k_final(float* __restrict__ dep) {
    int idx4 = blockIdx.x * 256 + threadIdx.x;   // 0..65535
    int b    = idx4 >> 14;
    float mx = __uint_as_float(g_mx[b]);
    float rd = 1.0f / (mx - __uint_as_float(g_mn[b]) + 1e-4f);
    float4 z = reinterpret_cast<const float4*>(dep)[idx4];
    float4 o;
    o.x = fminf(fmaxf((mx - z.x) * rd, 0.0f), 1.0f);
    o.y = fminf(fmaxf((mx - z.y) * rd, 0.0f), 1.0f);
    o.z = fminf(fmaxf((mx - z.z) * rd, 0.0f), 1.0f);
    o.w = fminf(fmaxf((mx - z.w) * rd, 0.0f), 1.0f);
    reinterpret_cast<float4*>(dep)[idx4] = o;
}

// ---------------- launch ------------------------------------------------------
extern "C" void kernel_launch(void* const* d_in, const int* in_sizes, int n_in,
                              void* d_out, int out_size) {
    const float* vertices = (const float*)d_in[0];
    const int*   faces    = (const int*)  d_in[1];
    const float* intr     = (const float*)d_in[2];
    const float* R        = (const float*)d_in[3];
    const float* t        = (const float*)d_in[4];
    const float* dist     = (const float*)d_in[5];

    float* out  = (float*)d_out;
    float* dep  = out;
    float* mask = out + B_ * NPIX;

    k_project<<<(B_ * V_ + 255) / 256, 256>>>(vertices, intr, R, t, dist);
    k_setup<<<(B_ * F_ + 255) / 256, 256>>>(faces);
    dim3 grid(RW / TILE, RW / TILE, B_);
    k_raster<<<grid, 256>>>(dep, mask);
    k_final<<<256, 256>>>(dep);
}